// round 7
// baseline (speedup 1.0000x reference)
#include <cuda_runtime.h>
#include <cuda_bf16.h>
#include <math.h>
#include <stdint.h>

#define B_  4
#define S_  2048
#define D_  1024
#define H_  16
#define DK_ 64
#define M_  (B_ * S_)

// ---------------------------------------------------------------------------
// Device-global scratch (no allocations allowed)
// ---------------------------------------------------------------------------
__device__ float g_cos[S_ * 32];
__device__ float g_sin[S_ * 32];

__device__ __nv_bfloat16 g_xhi[(size_t)M_ * D_];
__device__ __nv_bfloat16 g_xlo[(size_t)M_ * D_];
__device__ __nv_bfloat16 g_whi[4][(size_t)D_ * D_];   // q,k,v,o
__device__ __nv_bfloat16 g_wlo[4][(size_t)D_ * D_];
__device__ __nv_bfloat16 g_ohi[(size_t)M_ * D_];
__device__ __nv_bfloat16 g_olo[(size_t)M_ * D_];

__device__ __nv_bfloat16 g_Qhi[(size_t)B_ * H_ * S_ * DK_];
__device__ __nv_bfloat16 g_Qlo[(size_t)B_ * H_ * S_ * DK_];
__device__ __nv_bfloat16 g_Khi[(size_t)B_ * H_ * S_ * DK_];
__device__ __nv_bfloat16 g_Klo[(size_t)B_ * H_ * S_ * DK_];
__device__ __nv_bfloat16 g_Vhi[(size_t)B_ * H_ * S_ * DK_];
__device__ __nv_bfloat16 g_Vlo[(size_t)B_ * H_ * S_ * DK_];

// ---------------------------------------------------------------------------
// PTX helpers
// ---------------------------------------------------------------------------
__device__ __forceinline__ uint32_t smem_u32(const void* p) {
    uint32_t a;
    asm("{ .reg .u64 t; cvta.to.shared.u64 t, %1; cvt.u32.u64 %0, t; }"
        : "=r"(a) : "l"(p));
    return a;
}
__device__ __forceinline__ void ldsm_x4(uint32_t* r, uint32_t addr) {
    asm volatile("ldmatrix.sync.aligned.m8n8.x4.shared.b16 {%0,%1,%2,%3}, [%4];"
                 : "=r"(r[0]), "=r"(r[1]), "=r"(r[2]), "=r"(r[3]) : "r"(addr));
}
__device__ __forceinline__ void ldsm_x4_t(uint32_t* r, uint32_t addr) {
    asm volatile("ldmatrix.sync.aligned.m8n8.x4.trans.shared.b16 {%0,%1,%2,%3}, [%4];"
                 : "=r"(r[0]), "=r"(r[1]), "=r"(r[2]), "=r"(r[3]) : "r"(addr));
}
__device__ __forceinline__ void mma_bf16(float* d, const uint32_t* a,
                                         const uint32_t* b) {
    asm volatile(
        "mma.sync.aligned.m16n8k16.row.col.f32.bf16.bf16.f32 "
        "{%0,%1,%2,%3}, {%4,%5,%6,%7}, {%8,%9}, {%0,%1,%2,%3};"
        : "+f"(d[0]), "+f"(d[1]), "+f"(d[2]), "+f"(d[3])
        : "r"(a[0]), "r"(a[1]), "r"(a[2]), "r"(a[3]), "r"(b[0]), "r"(b[1]));
}
__device__ __forceinline__ void cp16(uint32_t dst, const void* src) {
    asm volatile("cp.async.cg.shared.global [%0], [%1], 16;"
                 :: "r"(dst), "l"(src) : "memory");
}
#define CP_COMMIT() asm volatile("cp.async.commit_group;" ::: "memory")
#define CP_WAIT0()  asm volatile("cp.async.wait_group 0;" ::: "memory")
#define CP_WAIT1()  asm volatile("cp.async.wait_group 1;" ::: "memory")

__device__ __forceinline__ uint32_t pack_bf16x2(float lo, float hi) {
    __nv_bfloat162 v = __halves2bfloat162(__float2bfloat16_rn(lo),
                                          __float2bfloat16_rn(hi));
    return *(uint32_t*)&v;
}

// ---------------------------------------------------------------------------
// RoPE table
// ---------------------------------------------------------------------------
__global__ void rope_table_kernel(const int* __restrict__ pos) {
    int idx = blockIdx.x * blockDim.x + threadIdx.x;
    if (idx >= S_ * 32) return;
    int s = idx >> 5;
    int p = idx & 31;
    float inv_freq = (float)pow(10000.0, -((double)(2 * p)) / 64.0);
    float ang = (float)pos[s] * inv_freq;
    g_cos[idx] = (float)cos((double)ang);
    g_sin[idx] = (float)sin((double)ang);
}

// ---------------------------------------------------------------------------
// fp32 -> bf16 hi/lo split. IDX: 0=x, 1..4=w[q,k,v,o]
// ---------------------------------------------------------------------------
template <int IDX>
__global__ void convert_split_kernel(const float* __restrict__ src, int n4) {
    int i = blockIdx.x * blockDim.x + threadIdx.x;
    if (i >= n4) return;
    __nv_bfloat16 *hi, *lo;
    if (IDX == 0) { hi = g_xhi; lo = g_xlo; }
    else          { hi = g_whi[IDX - 1]; lo = g_wlo[IDX - 1]; }

    float4 v = ((const float4*)src)[i];
    __nv_bfloat16 h0 = __float2bfloat16_rn(v.x);
    __nv_bfloat16 h1 = __float2bfloat16_rn(v.y);
    __nv_bfloat16 h2 = __float2bfloat16_rn(v.z);
    __nv_bfloat16 h3 = __float2bfloat16_rn(v.w);
    __nv_bfloat16 l0 = __float2bfloat16_rn(v.x - __bfloat162float(h0));
    __nv_bfloat16 l1 = __float2bfloat16_rn(v.y - __bfloat162float(h1));
    __nv_bfloat16 l2 = __float2bfloat16_rn(v.z - __bfloat162float(h2));
    __nv_bfloat16 l3 = __float2bfloat16_rn(v.w - __bfloat162float(h3));
    ((__nv_bfloat162*)hi)[2 * i]     = __halves2bfloat162(h0, h1);
    ((__nv_bfloat162*)hi)[2 * i + 1] = __halves2bfloat162(h2, h3);
    ((__nv_bfloat162*)lo)[2 * i]     = __halves2bfloat162(l0, l1);
    ((__nv_bfloat162*)lo)[2 * i + 1] = __halves2bfloat162(l2, l3);
}

// ---------------------------------------------------------------------------
// mma.sync bf16x3 GEMM, cp.async double-buffered.
// CTA tile 128x128, BK=64, 8 warps (4x2), warp tile 32x64.
// ---------------------------------------------------------------------------
#define T_STRIDE 144
#define T_BYTES  (128 * T_STRIDE)        // 18432
#define G_STAGE  (4 * T_BYTES)           // 73728
#define GEMM_SMEM (2 * G_STAGE)          // 147456

template <int MODE, int DST, int SRC, int WSEL>
__global__ void __launch_bounds__(256) mma_gemm_kernel(float* __restrict__ Cout) {
    extern __shared__ char sm[];
    const int tid  = threadIdx.x;
    const int w    = tid >> 5;
    const int lane = tid & 31;
    const int wm   = w >> 1;
    const int wn   = w & 1;
    const int n0   = blockIdx.x * 128;
    const int m0   = blockIdx.y * 128;

    const uint32_t sbase = smem_u32(sm);

    const __nv_bfloat16* srcs[4] = {
        ((SRC == 0) ? g_xhi : g_ohi) + (size_t)m0 * D_,
        ((SRC == 0) ? g_xlo : g_olo) + (size_t)m0 * D_,
        g_whi[WSEL] + (size_t)n0 * D_,
        g_wlo[WSEL] + (size_t)n0 * D_ };

    // async-load one BK=64 chunk (4 tiles) into stage buffer
    auto load_stage = [&](int kt, int st) {
        uint32_t sb = sbase + st * G_STAGE;
#pragma unroll
        for (int t = 0; t < 4; ++t) {
#pragma unroll
            for (int u = 0; u < 4; ++u) {
                int f = tid + u * 256;
                int r = f >> 3;
                int c = f & 7;
                cp16(sb + t * T_BYTES + r * T_STRIDE + c * 16,
                     srcs[t] + (size_t)r * D_ + kt * 64 + c * 8);
            }
        }
    };

    float d[2][8][4];
#pragma unroll
    for (int i = 0; i < 2; ++i)
#pragma unroll
        for (int j = 0; j < 8; ++j)
#pragma unroll
            for (int q = 0; q < 4; ++q) d[i][j][q] = 0.f;

    load_stage(0, 0);
    CP_COMMIT();

    for (int kt = 0; kt < 16; ++kt) {
        const int st = kt & 1;
        if (kt + 1 < 16) {
            load_stage(kt + 1, st ^ 1);
            CP_COMMIT();
            CP_WAIT1();
        } else {
            CP_WAIT0();
        }
        __syncthreads();

        const uint32_t oA0 = sbase + st * G_STAGE;
        const uint32_t oA1 = oA0 + T_BYTES;
        const uint32_t oB0 = oA0 + 2 * T_BYTES;
        const uint32_t oB1 = oA0 + 3 * T_BYTES;

#pragma unroll
        for (int ks = 0; ks < 4; ++ks) {
            const int k0 = ks * 16;
            uint32_t ah[2][4], al[2][4];
            {
                int arow = wm * 32 + (lane & 15);
                int acol = 2 * k0 + (lane >> 4) * 16;
#pragma unroll
                for (int i = 0; i < 2; ++i) {
                    uint32_t off = (uint32_t)((arow + i * 16) * T_STRIDE + acol);
                    ldsm_x4(ah[i], oA0 + off);
                    ldsm_x4(al[i], oA1 + off);
                }
            }
            uint32_t bh[8][2], bl[8][2];
            {
                int brow_l = (lane & 7) + ((lane >> 4) & 1) * 8;
                int bcol   = 2 * k0 + ((lane >> 3) & 1) * 16;
#pragma unroll
                for (int g = 0; g < 4; ++g) {
                    uint32_t off = (uint32_t)((wn * 64 + g * 16 + brow_l) * T_STRIDE + bcol);
                    uint32_t r4[4];
                    ldsm_x4(r4, oB0 + off);
                    bh[2 * g][0] = r4[0]; bh[2 * g][1] = r4[1];
                    bh[2 * g + 1][0] = r4[2]; bh[2 * g + 1][1] = r4[3];
                    ldsm_x4(r4, oB1 + off);
                    bl[2 * g][0] = r4[0]; bl[2 * g][1] = r4[1];
                    bl[2 * g + 1][0] = r4[2]; bl[2 * g + 1][1] = r4[3];
                }
            }
#pragma unroll
            for (int i = 0; i < 2; ++i)
#pragma unroll
                for (int j = 0; j < 8; ++j) {
                    mma_bf16(d[i][j], ah[i], bh[j]);
                    mma_bf16(d[i][j], al[i], bh[j]);
                    mma_bf16(d[i][j], ah[i], bl[j]);
                }
        }
        __syncthreads();
    }

    // Epilogue
#pragma unroll
    for (int i = 0; i < 2; ++i) {
        int mrow = m0 + wm * 32 + i * 16 + (lane >> 2);
#pragma unroll
        for (int half = 0; half < 2; ++half) {
            int m = mrow + half * 8;
            int b = m >> 11;
            int s = m & (S_ - 1);
#pragma unroll
            for (int j = 0; j < 8; ++j) {
                int n = n0 + wn * 64 + j * 8 + 2 * (lane & 3);
                float x0 = d[i][j][2 * half];
                float x1 = d[i][j][2 * half + 1];
                if (MODE == 0) {
                    *(float2*)(Cout + (size_t)m * D_ + n) = make_float2(x0, x1);
                } else {
                    int h = n >> 6;
                    int dk = n & 63;
                    float y0, y1;
                    if (MODE == 1) {
                        int p = dk >> 1;
                        float c = g_cos[s * 32 + p];
                        float sn = g_sin[s * 32 + p];
                        y0 = c * x0 - sn * x1;
                        y1 = sn * x0 + c * x1;
                    } else {
                        y0 = x0; y1 = x1;
                    }
                    if (DST == 0) { y0 *= 0.125f; y1 *= 0.125f; }
                    __nv_bfloat16 h0 = __float2bfloat16_rn(y0);
                    __nv_bfloat16 h1 = __float2bfloat16_rn(y1);
                    __nv_bfloat16 l0 = __float2bfloat16_rn(y0 - __bfloat162float(h0));
                    __nv_bfloat16 l1 = __float2bfloat16_rn(y1 - __bfloat162float(h1));
                    size_t idx = (((size_t)(b * H_ + h) * S_ + s) * DK_ + dk);
                    __nv_bfloat16 *Chi, *Clo;
                    if (DST == 0)      { Chi = g_Qhi; Clo = g_Qlo; }
                    else if (DST == 1) { Chi = g_Khi; Clo = g_Klo; }
                    else               { Chi = g_Vhi; Clo = g_Vlo; }
                    *(__nv_bfloat162*)(Chi + idx) = __halves2bfloat162(h0, h1);
                    *(__nv_bfloat162*)(Clo + idx) = __halves2bfloat162(l0, l1);
                }
            }
        }
    }
}

// ---------------------------------------------------------------------------
// Tensor-core flash attention (causal, bf16x3), cp.async double-buffered.
// CTA = 128 queries of one (b,h); 8 warps, each m16 x 64-dk.
// ---------------------------------------------------------------------------
#define A_TILE 9216                       // 64 rows * 144 B
#define A_STAGE (4 * A_TILE)              // 36864 (Khi,Klo,Vhi,Vlo)
#define ATT_SMEM (2 * A_STAGE)            // 73728

__global__ void __launch_bounds__(256) attn_mma_kernel() {
    extern __shared__ char asm_[];
    const int qb = gridDim.x - 1 - blockIdx.x;
    const int bh = blockIdx.y;
    const int tid = threadIdx.x;
    const int w = tid >> 5;
    const int lane = tid & 31;
    const int q0w = qb * 128 + w * 16;
    const size_t hb = (size_t)bh * S_ * DK_;

    const uint32_t sbase = smem_u32(asm_);

    const __nv_bfloat16* srcs[4] = { g_Khi + hb, g_Klo + hb, g_Vhi + hb, g_Vlo + hb };

    auto load_stage = [&](int kt, int st) {
        uint32_t sb = sbase + st * A_STAGE;
        const size_t roff = (size_t)(kt * 64) * 64;
#pragma unroll
        for (int t = 0; t < 4; ++t) {
#pragma unroll
            for (int u = 0; u < 2; ++u) {
                int f = tid + u * 256;
                int r = f >> 3;
                int c = f & 7;
                cp16(sb + t * A_TILE + r * 144 + c * 16,
                     srcs[t] + roff + (size_t)r * 64 + c * 8);
            }
        }
    };

    // Q fragments (pre-scaled by 1/8 in GEMM epilogue)
    uint32_t qh[4][4], ql[4][4];
    {
        const int r0 = q0w + (lane >> 2);
        const int c2 = (lane & 3) * 2;
        const __nv_bfloat16* Qh = g_Qhi + hb;
        const __nv_bfloat16* Ql = g_Qlo + hb;
#pragma unroll
        for (int t = 0; t < 4; ++t) {
            qh[t][0] = *(const uint32_t*)(Qh + (size_t)r0 * 64 + t * 16 + c2);
            qh[t][1] = *(const uint32_t*)(Qh + (size_t)(r0 + 8) * 64 + t * 16 + c2);
            qh[t][2] = *(const uint32_t*)(Qh + (size_t)r0 * 64 + t * 16 + 8 + c2);
            qh[t][3] = *(const uint32_t*)(Qh + (size_t)(r0 + 8) * 64 + t * 16 + 8 + c2);
            ql[t][0] = *(const uint32_t*)(Ql + (size_t)r0 * 64 + t * 16 + c2);
            ql[t][1] = *(const uint32_t*)(Ql + (size_t)(r0 + 8) * 64 + t * 16 + c2);
            ql[t][2] = *(const uint32_t*)(Ql + (size_t)r0 * 64 + t * 16 + 8 + c2);
            ql[t][3] = *(const uint32_t*)(Ql + (size_t)(r0 + 8) * 64 + t * 16 + 8 + c2);
        }
    }

    float o[8][4];
#pragma unroll
    for (int j = 0; j < 8; ++j)
#pragma unroll
        for (int q = 0; q < 4; ++q) o[j][q] = 0.f;
    float m0 = -3.0e38f, m1 = -3.0e38f, l0 = 0.f, l1 = 0.f;

    const int nkt = 2 * qb + 2;
    load_stage(0, 0);
    CP_COMMIT();

    for (int kt = 0; kt < nkt; ++kt) {
        const int k0 = kt * 64;
        const int st = kt & 1;
        if (kt + 1 < nkt) {
            load_stage(kt + 1, st ^ 1);
            CP_COMMIT();
            CP_WAIT1();
        } else {
            CP_WAIT0();
        }
        __syncthreads();

        if (q0w + 15 >= k0) {
            const uint32_t sKhi = sbase + st * A_STAGE;
            const uint32_t sKlo = sKhi + A_TILE;
            const uint32_t sVhi = sKhi + 2 * A_TILE;
            const uint32_t sVlo = sKhi + 3 * A_TILE;

            // ---- S = Q * K^T ----
            float s[8][4];
#pragma unroll
            for (int j = 0; j < 8; ++j)
#pragma unroll
                for (int q = 0; q < 4; ++q) s[j][q] = 0.f;

#pragma unroll
            for (int t = 0; t < 4; ++t) {
                uint32_t kh[8][2], kl[8][2];
                int brow = (lane & 7) + ((lane >> 4) & 1) * 8;
                int bcol = t * 32 + ((lane >> 3) & 1) * 16;
#pragma unroll
                for (int g = 0; g < 4; ++g) {
                    uint32_t off = (uint32_t)((g * 16 + brow) * 144 + bcol);
                    uint32_t r4[4];
                    ldsm_x4(r4, sKhi + off);
                    kh[2 * g][0] = r4[0]; kh[2 * g][1] = r4[1];
                    kh[2 * g + 1][0] = r4[2]; kh[2 * g + 1][1] = r4[3];
                    ldsm_x4(r4, sKlo + off);
                    kl[2 * g][0] = r4[0]; kl[2 * g][1] = r4[1];
                    kl[2 * g + 1][0] = r4[2]; kl[2 * g + 1][1] = r4[3];
                }
#pragma unroll
                for (int j = 0; j < 8; ++j) {
                    mma_bf16(s[j], qh[t], kh[j]);
                    mma_bf16(s[j], ql[t], kh[j]);
                    mma_bf16(s[j], qh[t], kl[j]);
                }
            }

            // ---- causal mask ----
            const int r0 = q0w + (lane >> 2);
            if (k0 + 63 > q0w) {
#pragma unroll
                for (int j = 0; j < 8; ++j) {
                    int col = k0 + 8 * j + 2 * (lane & 3);
                    if (col > r0)         s[j][0] = -3.0e38f;
                    if (col + 1 > r0)     s[j][1] = -3.0e38f;
                    if (col > r0 + 8)     s[j][2] = -3.0e38f;
                    if (col + 1 > r0 + 8) s[j][3] = -3.0e38f;
                }
            }

            // ---- online softmax ----
            float mx0 = -3.0e38f, mx1 = -3.0e38f;
#pragma unroll
            for (int j = 0; j < 8; ++j) {
                mx0 = fmaxf(mx0, fmaxf(s[j][0], s[j][1]));
                mx1 = fmaxf(mx1, fmaxf(s[j][2], s[j][3]));
            }
            mx0 = fmaxf(mx0, __shfl_xor_sync(0xffffffffu, mx0, 1));
            mx0 = fmaxf(mx0, __shfl_xor_sync(0xffffffffu, mx0, 2));
            mx1 = fmaxf(mx1, __shfl_xor_sync(0xffffffffu, mx1, 1));
            mx1 = fmaxf(mx1, __shfl_xor_sync(0xffffffffu, mx1, 2));
            float mn0 = fmaxf(m0, mx0), mn1 = fmaxf(m1, mx1);
            float a0 = __expf(m0 - mn0), a1 = __expf(m1 - mn1);

            uint32_t Ph[8][2], Pl[8][2];
            float sum0 = 0.f, sum1 = 0.f;
#pragma unroll
            for (int j = 0; j < 8; ++j) {
                float p0 = __expf(s[j][0] - mn0);
                float p1 = __expf(s[j][1] - mn0);
                float p2 = __expf(s[j][2] - mn1);
                float p3 = __expf(s[j][3] - mn1);
                sum0 += p0 + p1;
                sum1 += p2 + p3;
                __nv_bfloat16 h0 = __float2bfloat16_rn(p0), h1 = __float2bfloat16_rn(p1);
                __nv_bfloat16 h2 = __float2bfloat16_rn(p2), h3 = __float2bfloat16_rn(p3);
                __nv_bfloat162 vh01 = __halves2bfloat162(h0, h1);
                __nv_bfloat162 vh23 = __halves2bfloat162(h2, h3);
                Ph[j][0] = *(uint32_t*)&vh01;
                Ph[j][1] = *(uint32_t*)&vh23;
                Pl[j][0] = pack_bf16x2(p0 - __bfloat162float(h0), p1 - __bfloat162float(h1));
                Pl[j][1] = pack_bf16x2(p2 - __bfloat162float(h2), p3 - __bfloat162float(h3));
            }
            sum0 += __shfl_xor_sync(0xffffffffu, sum0, 1);
            sum0 += __shfl_xor_sync(0xffffffffu, sum0, 2);
            sum1 += __shfl_xor_sync(0xffffffffu, sum1, 1);
            sum1 += __shfl_xor_sync(0xffffffffu, sum1, 2);
            l0 = l0 * a0 + sum0;
            l1 = l1 * a1 + sum1;
            m0 = mn0; m1 = mn1;
#pragma unroll
            for (int j = 0; j < 8; ++j) {
                o[j][0] *= a0; o[j][1] *= a0; o[j][2] *= a1; o[j][3] *= a1;
            }

            // ---- O += P * V ----
#pragma unroll
            for (int t = 0; t < 4; ++t) {
                uint32_t ap[4] = { Ph[2 * t][0], Ph[2 * t][1],
                                   Ph[2 * t + 1][0], Ph[2 * t + 1][1] };
                uint32_t alr[4] = { Pl[2 * t][0], Pl[2 * t][1],
                                    Pl[2 * t + 1][0], Pl[2 * t + 1][1] };
                uint32_t vh[8][2], vl[8][2];
                int vrow = t * 16 + (lane & 15);
#pragma unroll
                for (int g = 0; g < 4; ++g) {
                    uint32_t off = (uint32_t)(vrow * 144 + (g * 16 + (lane >> 4) * 8) * 2);
                    uint32_t r4[4];
                    ldsm_x4_t(r4, sVhi + off);
                    vh[2 * g][0] = r4[0]; vh[2 * g][1] = r4[1];
                    vh[2 * g + 1][0] = r4[2]; vh[2 * g + 1][1] = r4[3];
                    ldsm_x4_t(r4, sVlo + off);
                    vl[2 * g][0] = r4[0]; vl[2 * g][1] = r4[1];
                    vl[2 * g + 1][0] = r4[2]; vl[2 * g + 1][1] = r4[3];
                }
#pragma unroll
                for (int j = 0; j < 8; ++j) {
                    mma_bf16(o[j], ap, vh[j]);
                    mma_bf16(o[j], alr, vh[j]);
                    mma_bf16(o[j], ap, vl[j]);
                }
            }
        }
        __syncthreads();
    }

    // ---- epilogue ----
    const float inv0 = 1.0f / l0, inv1 = 1.0f / l1;
    const int b = bh >> 4, h = bh & 15;
    const int s0 = q0w + (lane >> 2);
    const int c2 = 2 * (lane & 3);
#pragma unroll
    for (int j = 0; j < 8; ++j) {
        int dk = 8 * j + c2;
        {
            float y0 = o[j][0] * inv0, y1 = o[j][1] * inv0;
            __nv_bfloat16 h0 = __float2bfloat16_rn(y0), h1 = __float2bfloat16_rn(y1);
            size_t idx = ((size_t)(b * S_) + s0) * D_ + h * 64 + dk;
            *(__nv_bfloat162*)(g_ohi + idx) = __halves2bfloat162(h0, h1);
            *(uint32_t*)(g_olo + idx) =
                pack_bf16x2(y0 - __bfloat162float(h0), y1 - __bfloat162float(h1));
        }
        {
            float y0 = o[j][2] * inv1, y1 = o[j][3] * inv1;
            __nv_bfloat16 h0 = __float2bfloat16_rn(y0), h1 = __float2bfloat16_rn(y1);
            size_t idx = ((size_t)(b * S_) + s0 + 8) * D_ + h * 64 + dk;
            *(__nv_bfloat162*)(g_ohi + idx) = __halves2bfloat162(h0, h1);
            *(uint32_t*)(g_olo + idx) =
                pack_bf16x2(y0 - __bfloat162float(h0), y1 - __bfloat162float(h1));
        }
    }
}

// ---------------------------------------------------------------------------
// Launch
// ---------------------------------------------------------------------------
extern "C" void kernel_launch(void* const* d_in, const int* in_sizes, int n_in,
                              void* d_out, int out_size) {
    const float* x   = (const float*)d_in[0];
    const int*   pos = (const int*)d_in[1];
    const float* wq  = (const float*)d_in[2];
    const float* wk  = (const float*)d_in[3];
    const float* wv  = (const float*)d_in[4];
    const float* wo  = (const float*)d_in[5];
    float* out = (float*)d_out;
    (void)in_sizes; (void)n_in; (void)out_size;

    cudaFuncSetAttribute((const void*)mma_gemm_kernel<1, 0, 0, 0>,
                         cudaFuncAttributeMaxDynamicSharedMemorySize, GEMM_SMEM);
    cudaFuncSetAttribute((const void*)mma_gemm_kernel<1, 1, 0, 1>,
                         cudaFuncAttributeMaxDynamicSharedMemorySize, GEMM_SMEM);
    cudaFuncSetAttribute((const void*)mma_gemm_kernel<2, 2, 0, 2>,
                         cudaFuncAttributeMaxDynamicSharedMemorySize, GEMM_SMEM);
    cudaFuncSetAttribute((const void*)mma_gemm_kernel<0, 3, 1, 3>,
                         cudaFuncAttributeMaxDynamicSharedMemorySize, GEMM_SMEM);
    cudaFuncSetAttribute((const void*)attn_mma_kernel,
                         cudaFuncAttributeMaxDynamicSharedMemorySize, ATT_SMEM);

    // 1. RoPE tables
    rope_table_kernel<<<(S_ * 32 + 255) / 256, 256>>>(pos);

    // 2. bf16 hi/lo splits of x and weights
    {
        int n4x = (M_ * D_) / 4, n4w = (D_ * D_) / 4;
        convert_split_kernel<0><<<(n4x + 255) / 256, 256>>>(x, n4x);
        convert_split_kernel<1><<<(n4w + 255) / 256, 256>>>(wq, n4w);
        convert_split_kernel<2><<<(n4w + 255) / 256, 256>>>(wk, n4w);
        convert_split_kernel<3><<<(n4w + 255) / 256, 256>>>(wv, n4w);
        convert_split_kernel<4><<<(n4w + 255) / 256, 256>>>(wo, n4w);
    }

    // 3. QKV projections (RoPE + bf16 split fused)
    dim3 ggrid(D_ / 128, M_ / 128);
    mma_gemm_kernel<1, 0, 0, 0><<<ggrid, 256, GEMM_SMEM>>>(nullptr);
    mma_gemm_kernel<1, 1, 0, 1><<<ggrid, 256, GEMM_SMEM>>>(nullptr);
    mma_gemm_kernel<2, 2, 0, 2><<<ggrid, 256, GEMM_SMEM>>>(nullptr);

    // 4. Tensor-core causal flash attention -> g_ohi/g_olo
    attn_mma_kernel<<<dim3(S_ / 128, B_ * H_), 256, ATT_SMEM>>>();

    // 5. Output projection -> d_out
    mma_gemm_kernel<0, 3, 1, 3><<<ggrid, 256, GEMM_SMEM>>>(out);
}

// round 8
// speedup vs baseline: 1.1806x; 1.1806x over previous
#include <cuda_runtime.h>
#include <cuda_bf16.h>
#include <cuda_fp16.h>
#include <math.h>
#include <stdint.h>

#define B_  4
#define S_  2048
#define D_  1024
#define H_  16
#define DK_ 64
#define M_  (B_ * S_)

// ---------------------------------------------------------------------------
// Device-global scratch
// ---------------------------------------------------------------------------
__device__ float g_cos[S_ * 32];
__device__ float g_sin[S_ * 32];

__device__ __nv_bfloat16 g_xhi[(size_t)M_ * D_];
__device__ __nv_bfloat16 g_xlo[(size_t)M_ * D_];
__device__ __nv_bfloat16 g_whi[4][(size_t)D_ * D_];   // q,k,v,o
__device__ __nv_bfloat16 g_wlo[4][(size_t)D_ * D_];
__device__ __nv_bfloat16 g_ohi[(size_t)M_ * D_];
__device__ __nv_bfloat16 g_olo[(size_t)M_ * D_];

// Q/K/V in [b,h,s,dk] fp16. Q: hi/lo (pre-scaled 1/8). K: single. V: hi/lo.
__device__ __half g_Qh[(size_t)B_ * H_ * S_ * DK_];
__device__ __half g_Ql[(size_t)B_ * H_ * S_ * DK_];
__device__ __half g_Kh[(size_t)B_ * H_ * S_ * DK_];
__device__ __half g_Vh[(size_t)B_ * H_ * S_ * DK_];
__device__ __half g_Vl[(size_t)B_ * H_ * S_ * DK_];

// ---------------------------------------------------------------------------
// PTX helpers
// ---------------------------------------------------------------------------
__device__ __forceinline__ uint32_t smem_u32(const void* p) {
    uint32_t a;
    asm("{ .reg .u64 t; cvta.to.shared.u64 t, %1; cvt.u32.u64 %0, t; }"
        : "=r"(a) : "l"(p));
    return a;
}
__device__ __forceinline__ void ldsm_x4(uint32_t* r, uint32_t addr) {
    asm volatile("ldmatrix.sync.aligned.m8n8.x4.shared.b16 {%0,%1,%2,%3}, [%4];"
                 : "=r"(r[0]), "=r"(r[1]), "=r"(r[2]), "=r"(r[3]) : "r"(addr));
}
__device__ __forceinline__ void ldsm_x4_t(uint32_t* r, uint32_t addr) {
    asm volatile("ldmatrix.sync.aligned.m8n8.x4.trans.shared.b16 {%0,%1,%2,%3}, [%4];"
                 : "=r"(r[0]), "=r"(r[1]), "=r"(r[2]), "=r"(r[3]) : "r"(addr));
}
__device__ __forceinline__ void mma_bf16(float* d, const uint32_t* a,
                                         const uint32_t* b) {
    asm volatile(
        "mma.sync.aligned.m16n8k16.row.col.f32.bf16.bf16.f32 "
        "{%0,%1,%2,%3}, {%4,%5,%6,%7}, {%8,%9}, {%0,%1,%2,%3};"
        : "+f"(d[0]), "+f"(d[1]), "+f"(d[2]), "+f"(d[3])
        : "r"(a[0]), "r"(a[1]), "r"(a[2]), "r"(a[3]), "r"(b[0]), "r"(b[1]));
}
__device__ __forceinline__ void mma_f16(float* d, const uint32_t* a,
                                        const uint32_t* b) {
    asm volatile(
        "mma.sync.aligned.m16n8k16.row.col.f32.f16.f16.f32 "
        "{%0,%1,%2,%3}, {%4,%5,%6,%7}, {%8,%9}, {%0,%1,%2,%3};"
        : "+f"(d[0]), "+f"(d[1]), "+f"(d[2]), "+f"(d[3])
        : "r"(a[0]), "r"(a[1]), "r"(a[2]), "r"(a[3]), "r"(b[0]), "r"(b[1]));
}
__device__ __forceinline__ void cp16(uint32_t dst, const void* src) {
    asm volatile("cp.async.cg.shared.global [%0], [%1], 16;"
                 :: "r"(dst), "l"(src) : "memory");
}
#define CP_COMMIT() asm volatile("cp.async.commit_group;" ::: "memory")
#define CP_WAIT0()  asm volatile("cp.async.wait_group 0;" ::: "memory")
#define CP_WAIT1()  asm volatile("cp.async.wait_group 1;" ::: "memory")

__device__ __forceinline__ uint32_t pack_h2(__half a, __half b) {
    __half2 v = __halves2half2(a, b);
    return *(uint32_t*)&v;
}

// ---------------------------------------------------------------------------
// RoPE table
// ---------------------------------------------------------------------------
__global__ void rope_table_kernel(const int* __restrict__ pos) {
    int idx = blockIdx.x * blockDim.x + threadIdx.x;
    if (idx >= S_ * 32) return;
    int s = idx >> 5;
    int p = idx & 31;
    float inv_freq = (float)pow(10000.0, -((double)(2 * p)) / 64.0);
    float ang = (float)pos[s] * inv_freq;
    g_cos[idx] = (float)cos((double)ang);
    g_sin[idx] = (float)sin((double)ang);
}

// ---------------------------------------------------------------------------
// Single fused fp32 -> bf16 hi/lo split for x and all 4 weights.
// i indexes float4s: [0, 2097152) = x, then 4 x 262144 = wq,wk,wv,wo.
// ---------------------------------------------------------------------------
__global__ void convert_all_kernel(const float* __restrict__ x,
                                   const float* __restrict__ wq,
                                   const float* __restrict__ wk,
                                   const float* __restrict__ wv,
                                   const float* __restrict__ wo) {
    int i = blockIdx.x * blockDim.x + threadIdx.x;
    if (i >= 2097152 + 4 * 262144) return;
    const float* src;
    __nv_bfloat16 *hi, *lo;
    size_t off;
    if (i < 2097152) {
        src = x; hi = g_xhi; lo = g_xlo; off = i;
    } else {
        int j = i - 2097152;
        int wsel = j >> 18;
        off = j & 262143;
        src = (wsel == 0) ? wq : (wsel == 1) ? wk : (wsel == 2) ? wv : wo;
        hi = g_whi[wsel]; lo = g_wlo[wsel];
    }
    float4 v = ((const float4*)src)[off];
    __nv_bfloat16 h0 = __float2bfloat16_rn(v.x);
    __nv_bfloat16 h1 = __float2bfloat16_rn(v.y);
    __nv_bfloat16 h2 = __float2bfloat16_rn(v.z);
    __nv_bfloat16 h3 = __float2bfloat16_rn(v.w);
    __nv_bfloat16 l0 = __float2bfloat16_rn(v.x - __bfloat162float(h0));
    __nv_bfloat16 l1 = __float2bfloat16_rn(v.y - __bfloat162float(h1));
    __nv_bfloat16 l2 = __float2bfloat16_rn(v.z - __bfloat162float(h2));
    __nv_bfloat16 l3 = __float2bfloat16_rn(v.w - __bfloat162float(h3));
    ((__nv_bfloat162*)hi)[2 * off]     = __halves2bfloat162(h0, h1);
    ((__nv_bfloat162*)hi)[2 * off + 1] = __halves2bfloat162(h2, h3);
    ((__nv_bfloat162*)lo)[2 * off]     = __halves2bfloat162(l0, l1);
    ((__nv_bfloat162*)lo)[2 * off + 1] = __halves2bfloat162(l2, l3);
}

// ---------------------------------------------------------------------------
// Shared GEMM body pieces (bf16x3, cp.async double-buffered)
// ---------------------------------------------------------------------------
#define T_STRIDE 144
#define T_BYTES  (128 * T_STRIDE)
#define G_STAGE  (4 * T_BYTES)
#define GEMM_SMEM (2 * G_STAGE)

// ---------------------------------------------------------------------------
// Fused QKV GEMM: z = blockIdx.z selects weight + epilogue.
// z=0: Q = RoPE(x Wq^T)/8 -> fp16 hi/lo   z=1: K = RoPE(x Wk^T) -> fp16
// z=2: V = x Wv^T -> fp16 hi/lo           (all scattered to [b,h,s,dk])
// ---------------------------------------------------------------------------
__global__ void __launch_bounds__(256) qkv_gemm_kernel() {
    extern __shared__ char sm[];
    const int tid  = threadIdx.x;
    const int w    = tid >> 5;
    const int lane = tid & 31;
    const int wm   = w >> 1;
    const int wn   = w & 1;
    const int n0   = blockIdx.x * 128;
    const int m0   = blockIdx.y * 128;
    const int z    = blockIdx.z;

    const uint32_t sbase = smem_u32(sm);

    const __nv_bfloat16* srcs[4] = {
        g_xhi + (size_t)m0 * D_, g_xlo + (size_t)m0 * D_,
        g_whi[z] + (size_t)n0 * D_, g_wlo[z] + (size_t)n0 * D_ };

    auto load_stage = [&](int kt, int st) {
        uint32_t sb = sbase + st * G_STAGE;
#pragma unroll
        for (int t = 0; t < 4; ++t) {
#pragma unroll
            for (int u = 0; u < 4; ++u) {
                int f = tid + u * 256;
                int r = f >> 3;
                int c = f & 7;
                cp16(sb + t * T_BYTES + r * T_STRIDE + c * 16,
                     srcs[t] + (size_t)r * D_ + kt * 64 + c * 8);
            }
        }
    };

    float d[2][8][4];
#pragma unroll
    for (int i = 0; i < 2; ++i)
#pragma unroll
        for (int j = 0; j < 8; ++j)
#pragma unroll
            for (int q = 0; q < 4; ++q) d[i][j][q] = 0.f;

    load_stage(0, 0);
    CP_COMMIT();

    for (int kt = 0; kt < 16; ++kt) {
        const int st = kt & 1;
        if (kt + 1 < 16) {
            load_stage(kt + 1, st ^ 1);
            CP_COMMIT();
            CP_WAIT1();
        } else {
            CP_WAIT0();
        }
        __syncthreads();

        const uint32_t oA0 = sbase + st * G_STAGE;
        const uint32_t oA1 = oA0 + T_BYTES;
        const uint32_t oB0 = oA0 + 2 * T_BYTES;
        const uint32_t oB1 = oA0 + 3 * T_BYTES;

#pragma unroll
        for (int ks = 0; ks < 4; ++ks) {
            const int k0 = ks * 16;
            uint32_t ah[2][4], al[2][4];
            {
                int arow = wm * 32 + (lane & 15);
                int acol = 2 * k0 + (lane >> 4) * 16;
#pragma unroll
                for (int i = 0; i < 2; ++i) {
                    uint32_t off = (uint32_t)((arow + i * 16) * T_STRIDE + acol);
                    ldsm_x4(ah[i], oA0 + off);
                    ldsm_x4(al[i], oA1 + off);
                }
            }
            uint32_t bh[8][2], bl[8][2];
            {
                int brow_l = (lane & 7) + ((lane >> 4) & 1) * 8;
                int bcol   = 2 * k0 + ((lane >> 3) & 1) * 16;
#pragma unroll
                for (int g = 0; g < 4; ++g) {
                    uint32_t off = (uint32_t)((wn * 64 + g * 16 + brow_l) * T_STRIDE + bcol);
                    uint32_t r4[4];
                    ldsm_x4(r4, oB0 + off);
                    bh[2 * g][0] = r4[0]; bh[2 * g][1] = r4[1];
                    bh[2 * g + 1][0] = r4[2]; bh[2 * g + 1][1] = r4[3];
                    ldsm_x4(r4, oB1 + off);
                    bl[2 * g][0] = r4[0]; bl[2 * g][1] = r4[1];
                    bl[2 * g + 1][0] = r4[2]; bl[2 * g + 1][1] = r4[3];
                }
            }
#pragma unroll
            for (int i = 0; i < 2; ++i)
#pragma unroll
                for (int j = 0; j < 8; ++j) {
                    mma_bf16(d[i][j], ah[i], bh[j]);
                    mma_bf16(d[i][j], al[i], bh[j]);
                    mma_bf16(d[i][j], ah[i], bl[j]);
                }
        }
        __syncthreads();
    }

    // Epilogue: RoPE (z<2) + fp16 split + scatter to [b,h,s,dk]
#pragma unroll
    for (int i = 0; i < 2; ++i) {
        int mrow = m0 + wm * 32 + i * 16 + (lane >> 2);
#pragma unroll
        for (int half = 0; half < 2; ++half) {
            int m = mrow + half * 8;
            int b = m >> 11;
            int s = m & (S_ - 1);
#pragma unroll
            for (int j = 0; j < 8; ++j) {
                int n = n0 + wn * 64 + j * 8 + 2 * (lane & 3);
                float x0 = d[i][j][2 * half];
                float x1 = d[i][j][2 * half + 1];
                int h = n >> 6;
                int dk = n & 63;
                float y0, y1;
                if (z != 2) {
                    int p = dk >> 1;
                    float c = g_cos[s * 32 + p];
                    float sn = g_sin[s * 32 + p];
                    y0 = c * x0 - sn * x1;
                    y1 = sn * x0 + c * x1;
                } else {
                    y0 = x0; y1 = x1;
                }
                if (z == 0) { y0 *= 0.125f; y1 *= 0.125f; }
                size_t idx = (((size_t)(b * H_ + h) * S_ + s) * DK_ + dk);
                __half h0 = __float2half_rn(y0);
                __half h1 = __float2half_rn(y1);
                if (z == 0) {
                    *(uint32_t*)(g_Qh + idx) = pack_h2(h0, h1);
                    *(uint32_t*)(g_Ql + idx) =
                        pack_h2(__float2half_rn(y0 - __half2float(h0)),
                                __float2half_rn(y1 - __half2float(h1)));
                } else if (z == 1) {
                    *(uint32_t*)(g_Kh + idx) = pack_h2(h0, h1);
                } else {
                    *(uint32_t*)(g_Vh + idx) = pack_h2(h0, h1);
                    *(uint32_t*)(g_Vl + idx) =
                        pack_h2(__float2half_rn(y0 - __half2float(h0)),
                                __float2half_rn(y1 - __half2float(h1)));
                }
            }
        }
    }
}

// ---------------------------------------------------------------------------
// Output projection GEMM (bf16x3): out = O Wo^T, fp32 row-major store.
// ---------------------------------------------------------------------------
__global__ void __launch_bounds__(256) out_gemm_kernel(float* __restrict__ Cout) {
    extern __shared__ char sm[];
    const int tid  = threadIdx.x;
    const int w    = tid >> 5;
    const int lane = tid & 31;
    const int wm   = w >> 1;
    const int wn   = w & 1;
    const int n0   = blockIdx.x * 128;
    const int m0   = blockIdx.y * 128;

    const uint32_t sbase = smem_u32(sm);

    const __nv_bfloat16* srcs[4] = {
        g_ohi + (size_t)m0 * D_, g_olo + (size_t)m0 * D_,
        g_whi[3] + (size_t)n0 * D_, g_wlo[3] + (size_t)n0 * D_ };

    auto load_stage = [&](int kt, int st) {
        uint32_t sb = sbase + st * G_STAGE;
#pragma unroll
        for (int t = 0; t < 4; ++t) {
#pragma unroll
            for (int u = 0; u < 4; ++u) {
                int f = tid + u * 256;
                int r = f >> 3;
                int c = f & 7;
                cp16(sb + t * T_BYTES + r * T_STRIDE + c * 16,
                     srcs[t] + (size_t)r * D_ + kt * 64 + c * 8);
            }
        }
    };

    float d[2][8][4];
#pragma unroll
    for (int i = 0; i < 2; ++i)
#pragma unroll
        for (int j = 0; j < 8; ++j)
#pragma unroll
            for (int q = 0; q < 4; ++q) d[i][j][q] = 0.f;

    load_stage(0, 0);
    CP_COMMIT();

    for (int kt = 0; kt < 16; ++kt) {
        const int st = kt & 1;
        if (kt + 1 < 16) {
            load_stage(kt + 1, st ^ 1);
            CP_COMMIT();
            CP_WAIT1();
        } else {
            CP_WAIT0();
        }
        __syncthreads();

        const uint32_t oA0 = sbase + st * G_STAGE;
        const uint32_t oA1 = oA0 + T_BYTES;
        const uint32_t oB0 = oA0 + 2 * T_BYTES;
        const uint32_t oB1 = oA0 + 3 * T_BYTES;

#pragma unroll
        for (int ks = 0; ks < 4; ++ks) {
            const int k0 = ks * 16;
            uint32_t ah[2][4], al[2][4];
            {
                int arow = wm * 32 + (lane & 15);
                int acol = 2 * k0 + (lane >> 4) * 16;
#pragma unroll
                for (int i = 0; i < 2; ++i) {
                    uint32_t off = (uint32_t)((arow + i * 16) * T_STRIDE + acol);
                    ldsm_x4(ah[i], oA0 + off);
                    ldsm_x4(al[i], oA1 + off);
                }
            }
            uint32_t bh[8][2], bl[8][2];
            {
                int brow_l = (lane & 7) + ((lane >> 4) & 1) * 8;
                int bcol   = 2 * k0 + ((lane >> 3) & 1) * 16;
#pragma unroll
                for (int g = 0; g < 4; ++g) {
                    uint32_t off = (uint32_t)((wn * 64 + g * 16 + brow_l) * T_STRIDE + bcol);
                    uint32_t r4[4];
                    ldsm_x4(r4, oB0 + off);
                    bh[2 * g][0] = r4[0]; bh[2 * g][1] = r4[1];
                    bh[2 * g + 1][0] = r4[2]; bh[2 * g + 1][1] = r4[3];
                    ldsm_x4(r4, oB1 + off);
                    bl[2 * g][0] = r4[0]; bl[2 * g][1] = r4[1];
                    bl[2 * g + 1][0] = r4[2]; bl[2 * g + 1][1] = r4[3];
                }
            }
#pragma unroll
            for (int i = 0; i < 2; ++i)
#pragma unroll
                for (int j = 0; j < 8; ++j) {
                    mma_bf16(d[i][j], ah[i], bh[j]);
                    mma_bf16(d[i][j], al[i], bh[j]);
                    mma_bf16(d[i][j], ah[i], bl[j]);
                }
        }
        __syncthreads();
    }

#pragma unroll
    for (int i = 0; i < 2; ++i) {
        int mrow = m0 + wm * 32 + i * 16 + (lane >> 2);
#pragma unroll
        for (int half = 0; half < 2; ++half) {
            int m = mrow + half * 8;
#pragma unroll
            for (int j = 0; j < 8; ++j) {
                int n = n0 + wn * 64 + j * 8 + 2 * (lane & 3);
                *(float2*)(Cout + (size_t)m * D_ + n) =
                    make_float2(d[i][j][2 * half], d[i][j][2 * half + 1]);
            }
        }
    }
}

// ---------------------------------------------------------------------------
// Tensor-core flash attention (causal), fp16 path:
//   S = Qh*Kh + Ql*Kh  (K single fp16)
//   P quantized to fp16; l = sum of QUANTIZED p (normalization-consistent)
//   O += Ph*Vh + Ph*Vl (V fp16 hi/lo)
// CTA = 128 queries of one (b,h); 8 warps; 64-key double-buffered stages.
// ---------------------------------------------------------------------------
#define A_TILE 9216                       // 64 rows * 144 B
#define A_STAGE (3 * A_TILE)              // Kh, Vh, Vl
#define ATT_SMEM (2 * A_STAGE)            // 55296

__global__ void __launch_bounds__(256) attn_mma_kernel() {
    extern __shared__ char asm_[];
    const int qb = gridDim.x - 1 - blockIdx.x;
    const int bh = blockIdx.y;
    const int tid = threadIdx.x;
    const int w = tid >> 5;
    const int lane = tid & 31;
    const int q0w = qb * 128 + w * 16;
    const size_t hb = (size_t)bh * S_ * DK_;

    const uint32_t sbase = smem_u32(asm_);

    const __half* srcs[3] = { g_Kh + hb, g_Vh + hb, g_Vl + hb };

    auto load_stage = [&](int kt, int st) {
        uint32_t sb = sbase + st * A_STAGE;
        const size_t roff = (size_t)(kt * 64) * 64;
#pragma unroll
        for (int t = 0; t < 3; ++t) {
#pragma unroll
            for (int u = 0; u < 2; ++u) {
                int f = tid + u * 256;
                int r = f >> 3;
                int c = f & 7;
                cp16(sb + t * A_TILE + r * 144 + c * 16,
                     srcs[t] + roff + (size_t)r * 64 + c * 8);
            }
        }
    };

    // Q fragments (hi/lo fp16, pre-scaled by 1/8)
    uint32_t qh[4][4], ql[4][4];
    {
        const int r0 = q0w + (lane >> 2);
        const int c2 = (lane & 3) * 2;
        const __half* Qh = g_Qh + hb;
        const __half* Ql = g_Ql + hb;
#pragma unroll
        for (int t = 0; t < 4; ++t) {
            qh[t][0] = *(const uint32_t*)(Qh + (size_t)r0 * 64 + t * 16 + c2);
            qh[t][1] = *(const uint32_t*)(Qh + (size_t)(r0 + 8) * 64 + t * 16 + c2);
            qh[t][2] = *(const uint32_t*)(Qh + (size_t)r0 * 64 + t * 16 + 8 + c2);
            qh[t][3] = *(const uint32_t*)(Qh + (size_t)(r0 + 8) * 64 + t * 16 + 8 + c2);
            ql[t][0] = *(const uint32_t*)(Ql + (size_t)r0 * 64 + t * 16 + c2);
            ql[t][1] = *(const uint32_t*)(Ql + (size_t)(r0 + 8) * 64 + t * 16 + c2);
            ql[t][2] = *(const uint32_t*)(Ql + (size_t)r0 * 64 + t * 16 + 8 + c2);
            ql[t][3] = *(const uint32_t*)(Ql + (size_t)(r0 + 8) * 64 + t * 16 + 8 + c2);
        }
    }

    float o[8][4];
#pragma unroll
    for (int j = 0; j < 8; ++j)
#pragma unroll
        for (int q = 0; q < 4; ++q) o[j][q] = 0.f;
    float m0 = -3.0e38f, m1 = -3.0e38f, l0 = 0.f, l1 = 0.f;

    const int nkt = 2 * qb + 2;
    load_stage(0, 0);
    CP_COMMIT();

    for (int kt = 0; kt < nkt; ++kt) {
        const int k0 = kt * 64;
        const int st = kt & 1;
        if (kt + 1 < nkt) {
            load_stage(kt + 1, st ^ 1);
            CP_COMMIT();
            CP_WAIT1();
        } else {
            CP_WAIT0();
        }
        __syncthreads();

        if (q0w + 15 >= k0) {
            const uint32_t sKh = sbase + st * A_STAGE;
            const uint32_t sVh = sKh + A_TILE;
            const uint32_t sVl = sKh + 2 * A_TILE;

            // ---- S = Q * K^T (2 terms) ----
            float s[8][4];
#pragma unroll
            for (int j = 0; j < 8; ++j)
#pragma unroll
                for (int q = 0; q < 4; ++q) s[j][q] = 0.f;

#pragma unroll
            for (int t = 0; t < 4; ++t) {
                uint32_t kh[8][2];
                int brow = (lane & 7) + ((lane >> 4) & 1) * 8;
                int bcol = t * 32 + ((lane >> 3) & 1) * 16;
#pragma unroll
                for (int g = 0; g < 4; ++g) {
                    uint32_t off = (uint32_t)((g * 16 + brow) * 144 + bcol);
                    uint32_t r4[4];
                    ldsm_x4(r4, sKh + off);
                    kh[2 * g][0] = r4[0]; kh[2 * g][1] = r4[1];
                    kh[2 * g + 1][0] = r4[2]; kh[2 * g + 1][1] = r4[3];
                }
#pragma unroll
                for (int j = 0; j < 8; ++j) {
                    mma_f16(s[j], qh[t], kh[j]);
                    mma_f16(s[j], ql[t], kh[j]);
                }
            }

            // ---- causal mask ----
            const int r0 = q0w + (lane >> 2);
            if (k0 + 63 > q0w) {
#pragma unroll
                for (int j = 0; j < 8; ++j) {
                    int col = k0 + 8 * j + 2 * (lane & 3);
                    if (col > r0)         s[j][0] = -3.0e38f;
                    if (col + 1 > r0)     s[j][1] = -3.0e38f;
                    if (col > r0 + 8)     s[j][2] = -3.0e38f;
                    if (col + 1 > r0 + 8) s[j][3] = -3.0e38f;
                }
            }

            // ---- online softmax (l accumulates QUANTIZED p) ----
            float mx0 = -3.0e38f, mx1 = -3.0e38f;
#pragma unroll
            for (int j = 0; j < 8; ++j) {
                mx0 = fmaxf(mx0, fmaxf(s[j][0], s[j][1]));
                mx1 = fmaxf(mx1, fmaxf(s[j][2], s[j][3]));
            }
            mx0 = fmaxf(mx0, __shfl_xor_sync(0xffffffffu, mx0, 1));
            mx0 = fmaxf(mx0, __shfl_xor_sync(0xffffffffu, mx0, 2));
            mx1 = fmaxf(mx1, __shfl_xor_sync(0xffffffffu, mx1, 1));
            mx1 = fmaxf(mx1, __shfl_xor_sync(0xffffffffu, mx1, 2));
            float mn0 = fmaxf(m0, mx0), mn1 = fmaxf(m1, mx1);
            float a0 = __expf(m0 - mn0), a1 = __expf(m1 - mn1);

            uint32_t Ph[8][2];
            float sum0 = 0.f, sum1 = 0.f;
#pragma unroll
            for (int j = 0; j < 8; ++j) {
                __half h0 = __float2half_rn(__expf(s[j][0] - mn0));
                __half h1 = __float2half_rn(__expf(s[j][1] - mn0));
                __half h2 = __float2half_rn(__expf(s[j][2] - mn1));
                __half h3 = __float2half_rn(__expf(s[j][3] - mn1));
                sum0 += __half2float(h0) + __half2float(h1);
                sum1 += __half2float(h2) + __half2float(h3);
                Ph[j][0] = pack_h2(h0, h1);
                Ph[j][1] = pack_h2(h2, h3);
            }
            sum0 += __shfl_xor_sync(0xffffffffu, sum0, 1);
            sum0 += __shfl_xor_sync(0xffffffffu, sum0, 2);
            sum1 += __shfl_xor_sync(0xffffffffu, sum1, 1);
            sum1 += __shfl_xor_sync(0xffffffffu, sum1, 2);
            l0 = l0 * a0 + sum0;
            l1 = l1 * a1 + sum1;
            m0 = mn0; m1 = mn1;
#pragma unroll
            for (int j = 0; j < 8; ++j) {
                o[j][0] *= a0; o[j][1] *= a0; o[j][2] *= a1; o[j][3] *= a1;
            }

            // ---- O += P * V (2 terms) ----
#pragma unroll
            for (int t = 0; t < 4; ++t) {
                uint32_t ap[4] = { Ph[2 * t][0], Ph[2 * t][1],
                                   Ph[2 * t + 1][0], Ph[2 * t + 1][1] };
                uint32_t vh[8][2], vl[8][2];
                int vrow = t * 16 + (lane & 15);
#pragma unroll
                for (int g = 0; g < 4; ++g) {
                    uint32_t off = (uint32_t)(vrow * 144 + (g * 16 + (lane >> 4) * 8) * 2);
                    uint32_t r4[4];
                    ldsm_x4_t(r4, sVh + off);
                    vh[2 * g][0] = r4[0]; vh[2 * g][1] = r4[1];
                    vh[2 * g + 1][0] = r4[2]; vh[2 * g + 1][1] = r4[3];
                    ldsm_x4_t(r4, sVl + off);
                    vl[2 * g][0] = r4[0]; vl[2 * g][1] = r4[1];
                    vl[2 * g + 1][0] = r4[2]; vl[2 * g + 1][1] = r4[3];
                }
#pragma unroll
                for (int j = 0; j < 8; ++j) {
                    mma_f16(o[j], ap, vh[j]);
                    mma_f16(o[j], ap, vl[j]);
                }
            }
        }
        __syncthreads();
    }

    // ---- epilogue: normalize, bf16 hi/lo split, write [b,s,h*dk] ----
    const float inv0 = 1.0f / l0, inv1 = 1.0f / l1;
    const int b = bh >> 4, h = bh & 15;
    const int s0 = q0w + (lane >> 2);
    const int c2 = 2 * (lane & 3);
#pragma unroll
    for (int j = 0; j < 8; ++j) {
        int dk = 8 * j + c2;
        {
            float y0 = o[j][0] * inv0, y1 = o[j][1] * inv0;
            __nv_bfloat16 h0 = __float2bfloat16_rn(y0), h1 = __float2bfloat16_rn(y1);
            size_t idx = ((size_t)(b * S_) + s0) * D_ + h * 64 + dk;
            *(__nv_bfloat162*)(g_ohi + idx) = __halves2bfloat162(h0, h1);
            *(__nv_bfloat162*)(g_olo + idx) = __halves2bfloat162(
                __float2bfloat16_rn(y0 - __bfloat162float(h0)),
                __float2bfloat16_rn(y1 - __bfloat162float(h1)));
        }
        {
            float y0 = o[j][2] * inv1, y1 = o[j][3] * inv1;
            __nv_bfloat16 h0 = __float2bfloat16_rn(y0), h1 = __float2bfloat16_rn(y1);
            size_t idx = ((size_t)(b * S_) + s0 + 8) * D_ + h * 64 + dk;
            *(__nv_bfloat162*)(g_ohi + idx) = __halves2bfloat162(h0, h1);
            *(__nv_bfloat162*)(g_olo + idx) = __halves2bfloat162(
                __float2bfloat16_rn(y0 - __bfloat162float(h0)),
                __float2bfloat16_rn(y1 - __bfloat162float(h1)));
        }
    }
}

// ---------------------------------------------------------------------------
// Launch
// ---------------------------------------------------------------------------
extern "C" void kernel_launch(void* const* d_in, const int* in_sizes, int n_in,
                              void* d_out, int out_size) {
    const float* x   = (const float*)d_in[0];
    const int*   pos = (const int*)d_in[1];
    const float* wq  = (const float*)d_in[2];
    const float* wk  = (const float*)d_in[3];
    const float* wv  = (const float*)d_in[4];
    const float* wo  = (const float*)d_in[5];
    float* out = (float*)d_out;
    (void)in_sizes; (void)n_in; (void)out_size;

    cudaFuncSetAttribute((const void*)qkv_gemm_kernel,
                         cudaFuncAttributeMaxDynamicSharedMemorySize, GEMM_SMEM);
    cudaFuncSetAttribute((const void*)out_gemm_kernel,
                         cudaFuncAttributeMaxDynamicSharedMemorySize, GEMM_SMEM);
    cudaFuncSetAttribute((const void*)attn_mma_kernel,
                         cudaFuncAttributeMaxDynamicSharedMemorySize, ATT_SMEM);

    // 1. RoPE tables
    rope_table_kernel<<<(S_ * 32 + 255) / 256, 256>>>(pos);

    // 2. One fused bf16 hi/lo split (x + all 4 weights)
    {
        int total = 2097152 + 4 * 262144;
        convert_all_kernel<<<(total + 255) / 256, 256>>>(x, wq, wk, wv, wo);
    }

    // 3. Fused QKV projection (z selects Q/K/V; RoPE + fp16 split fused)
    qkv_gemm_kernel<<<dim3(D_ / 128, M_ / 128, 3), 256, GEMM_SMEM>>>();

    // 4. fp16 tensor-core causal flash attention -> g_ohi/g_olo
    attn_mma_kernel<<<dim3(S_ / 128, B_ * H_), 256, ATT_SMEM>>>();

    // 5. Output projection -> d_out
    out_gemm_kernel<<<dim3(D_ / 128, M_ / 128), 256, GEMM_SMEM>>>(out);
}